// round 10
// baseline (speedup 1.0000x reference)
#include <cuda_runtime.h>
#include <cuda_fp16.h>
#include <cstdint>
#include <math.h>

// Problem constants
#define BATCH 2
#define C 256
#define H 64
#define W 64
#define HW 4096
#define K2 9
#define CO 256
#define CK 2304        // C*K2
#define G 16           // channel groups for conv partial sums (16 ch each)

// Scratch (__device__ globals; allocation-free rule)
__device__ float  g_part[BATCH * G * 27 * HW];     // [b][g][o(27)][p]
__device__ __half g_vh[(size_t)BATCH * CK * HW];   // [b][ck][p]  p-contiguous fp16
__device__ __half g_wh[(size_t)CO * CK];           // W fp16, K-major rows of o
__device__ __half g_xt[(size_t)BATCH * HW * C];    // x transposed: [b][p][c] fp16
__device__ float  g_po[(size_t)BATCH * CO * HW];   // split-K partial output

// ---------------------------------------------------------------------------
// helpers
// ---------------------------------------------------------------------------
__device__ __forceinline__ uint32_t smem_u32(const void* p) {
    uint32_t a;
    asm("{ .reg .u64 t; cvta.to.shared.u64 t, %1; cvt.u32.u64 %0, t; }" : "=r"(a) : "l"(p));
    return a;
}
__device__ __forceinline__ void cp_async16(uint32_t dst, const void* src) {
    asm volatile("cp.async.cg.shared.global [%0], [%1], 16;" :: "r"(dst), "l"(src));
}
#define CP_COMMIT() asm volatile("cp.async.commit_group;" ::: "memory")
#define CP_WAIT(n)  asm volatile("cp.async.wait_group %0;" :: "n"(n) : "memory")
#define SWZ128(off) ((off) ^ (((off) >> 3) & 0x70))

#define LDSM4(r, addr) \
    asm volatile("ldmatrix.sync.aligned.m8n8.x4.shared.b16 {%0,%1,%2,%3}, [%4];" \
        : "=r"((r)[0]), "=r"((r)[1]), "=r"((r)[2]), "=r"((r)[3]) : "r"(addr))
#define LDSM4T(r, addr) \
    asm volatile("ldmatrix.sync.aligned.m8n8.x4.trans.shared.b16 {%0,%1,%2,%3}, [%4];" \
        : "=r"((r)[0]), "=r"((r)[1]), "=r"((r)[2]), "=r"((r)[3]) : "r"(addr))

__device__ __forceinline__ void mma16816(float c[4], const uint32_t a[4], const uint32_t b[2]) {
    asm volatile(
        "mma.sync.aligned.m16n8k16.row.col.f32.f16.f16.f32 "
        "{%0,%1,%2,%3}, {%4,%5,%6,%7}, {%8,%9}, {%0,%1,%2,%3};"
        : "+f"(c[0]), "+f"(c[1]), "+f"(c[2]), "+f"(c[3])
        : "r"(a[0]), "r"(a[1]), "r"(a[2]), "r"(a[3]), "r"(b[0]), "r"(b[1]));
}

__device__ __forceinline__ void h8_to_f(const __half* src, float* f) {
    const uint4 v = *(const uint4*)src;
    const __half2* h = (const __half2*)&v;
#pragma unroll
    for (int j = 0; j < 4; ++j) {
        const float2 t = __half22float2(h[j]);
        f[2 * j] = t.x; f[2 * j + 1] = t.y;
    }
}

// ---------------------------------------------------------------------------
// Kernel 1: blocks 0..255 conv (offset 18ch from res + mod 9ch from x);
// blocks 256..399 W->fp16; blocks 400..1423 transpose x -> g_xt[b][p][c] fp16.
// ---------------------------------------------------------------------------
__global__ __launch_bounds__(128)
void conv_offmod_kernel(const float* __restrict__ x,
                        const float* __restrict__ res,
                        const float* __restrict__ ow,   // [18][C][9]
                        const float* __restrict__ mw,   // [9][C][9]
                        const float* __restrict__ rw)   // [256][C][9]
{
    __shared__ __align__(16) float sw[16 * 27 * 12];    // 5184 floats (>= 64*33)

    const int tid  = threadIdx.x;
    const int bidx = blockIdx.x;

    if (bidx >= 400) {
        // transpose: tile 64 c x 32 p
        const int t  = bidx - 400;                 // 0..1023
        const int p0 = (t & 127) * 32;
        const int c0 = ((t >> 7) & 3) * 64;
        const int b  = t >> 9;
        float (*s32)[33] = (float(*)[33])sw;
        const int lane = tid & 31;
        const int wi   = tid >> 5;                 // 0..3
        const float* xb = x + ((size_t)(b * C + c0)) * HW + p0;
#pragma unroll
        for (int i = 0; i < 16; ++i) {
            const int cl = wi * 16 + i;
            s32[cl][lane] = xb[(size_t)cl * HW + lane];
        }
        __syncthreads();
        __half2* dst = (__half2*)(g_xt + ((size_t)(b * HW + p0)) * C + c0);
#pragma unroll
        for (int i = 0; i < 8; ++i) {
            const int pl = wi * 8 + i;
            dst[(size_t)pl * (C / 2) + lane] =
                __floats2half2_rn(s32[lane * 2][pl], s32[lane * 2 + 1][pl]);
        }
        return;
    }

    if (bidx >= 256) {
        // fused prep_w: convert reg_w to fp16
        const int n4 = CO * CK / 4;                // 147456 float4
        for (int i = (bidx - 256) * 128 + tid; i < n4; i += 144 * 128) {
            const float4 v = ((const float4*)rw)[i];
            __half2* dst = (__half2*)(g_wh + (size_t)i * 4);
            dst[0] = __floats2half2_rn(v.x, v.y);
            dst[1] = __floats2half2_rn(v.z, v.w);
        }
        return;
    }

    const int pblk = bidx & 7;
    const int g    = (bidx >> 3) & (G - 1);
    const int b    = bidx >> 7;
    const int p    = pblk * 512 + tid * 4;
    const int h    = p >> 6;
    const int w    = p & 63;

    const int cbase = g * 16;
    for (int i = tid; i < 16 * 243; i += 128) {
        const int ci = i / 243;
        const int t  = i % 243;
        const int c  = cbase + ci;
        const int o  = t / 9;
        const int tt = t % 9;
        float wv;
        if (o < 18) wv = ow[(size_t)o * CK + c * 9 + tt];
        else        wv = mw[(size_t)(o - 18) * CK + c * 9 + tt];
        sw[ci * 324 + o * 12 + tt] = wv;
    }
    __syncthreads();

    float* outp = g_part + (size_t)(b * G + g) * 27 * HW;

    // Pass A: 18 offset outputs from residual
    {
        float acc[18][4];
#pragma unroll
        for (int o = 0; o < 18; ++o)
#pragma unroll
            for (int j = 0; j < 4; ++j) acc[o][j] = 0.f;

        const float* rb = res + (size_t)b * C * HW;
        for (int ci = 0; ci < 16; ++ci) {
            const float* rc = rb + (size_t)(cbase + ci) * HW;
            float rv[18];
#pragma unroll
            for (int r = 0; r < 3; ++r) {
                const int hh = h + r - 1;
                const bool vy = ((unsigned)hh < 64u);
#pragma unroll
                for (int s = 0; s < 6; ++s) {
                    const int ww = w + s - 1;
                    const bool v = vy && ((unsigned)ww < 64u);
                    rv[r * 6 + s] = v ? rc[hh * 64 + ww] : 0.f;
                }
            }
            const float* swc = sw + ci * 324;
#pragma unroll
            for (int o = 0; o < 18; ++o) {
                const float4 wA = *(const float4*)(swc + o * 12);
                const float4 wB = *(const float4*)(swc + o * 12 + 4);
                const float  w8 = swc[o * 12 + 8];
#pragma unroll
                for (int j = 0; j < 4; ++j) {
                    acc[o][j] += wA.x * rv[j]      + wA.y * rv[j + 1]  + wA.z * rv[j + 2]
                               + wA.w * rv[j + 6]  + wB.x * rv[j + 7]  + wB.y * rv[j + 8]
                               + wB.z * rv[j + 12] + wB.w * rv[j + 13] + w8  * rv[j + 14];
                }
            }
        }
#pragma unroll
        for (int o = 0; o < 18; ++o) {
            float4 v; v.x = acc[o][0]; v.y = acc[o][1]; v.z = acc[o][2]; v.w = acc[o][3];
            *(float4*)(outp + o * HW + p) = v;
        }
    }

    // Pass B: 9 modulator outputs from x
    {
        float acc[9][4];
#pragma unroll
        for (int o = 0; o < 9; ++o)
#pragma unroll
            for (int j = 0; j < 4; ++j) acc[o][j] = 0.f;

        const float* xb = x + (size_t)b * C * HW;
        for (int ci = 0; ci < 16; ++ci) {
            const float* xc = xb + (size_t)(cbase + ci) * HW;
            float xv[18];
#pragma unroll
            for (int r = 0; r < 3; ++r) {
                const int hh = h + r - 1;
                const bool vy = ((unsigned)hh < 64u);
#pragma unroll
                for (int s = 0; s < 6; ++s) {
                    const int ww = w + s - 1;
                    const bool v = vy && ((unsigned)ww < 64u);
                    xv[r * 6 + s] = v ? xc[hh * 64 + ww] : 0.f;
                }
            }
            const float* swc = sw + ci * 324;
#pragma unroll
            for (int o = 0; o < 9; ++o) {
                const float4 wA = *(const float4*)(swc + (18 + o) * 12);
                const float4 wB = *(const float4*)(swc + (18 + o) * 12 + 4);
                const float  w8 = swc[(18 + o) * 12 + 8];
#pragma unroll
                for (int j = 0; j < 4; ++j) {
                    acc[o][j] += wA.x * xv[j]      + wA.y * xv[j + 1]  + wA.z * xv[j + 2]
                               + wA.w * xv[j + 6]  + wB.x * xv[j + 7]  + wB.y * xv[j + 8]
                               + wB.z * xv[j + 12] + wB.w * xv[j + 13] + w8  * xv[j + 14];
                }
            }
        }
#pragma unroll
        for (int o = 0; o < 9; ++o) {
            float4 v; v.x = acc[o][0]; v.y = acc[o][1]; v.z = acc[o][2]; v.w = acc[o][3];
            *(float4*)(outp + (18 + o) * HW + p) = v;
        }
    }
}

// ---------------------------------------------------------------------------
// Kernel 2: sampling v2 — dense row reads from g_xt[b][p][c].
// 288 threads: warp = tap k, lane = pixel. Each thread reads 4 fp16 rows
// (512B each, LDG.128 streams), fp32 bilinear, writes g_vh[b][ck][p].
// ---------------------------------------------------------------------------
__global__ __launch_bounds__(288)
void sample_kernel(const float* __restrict__ ob,   // [18]
                   const float* __restrict__ mb)   // [9]
{
    const int tid  = threadIdx.x;
    const int lane = tid & 31;
    const int k    = tid >> 5;           // 0..8
    const int b    = blockIdx.y;
    const int p    = blockIdx.x * 32 + lane;
    const int h    = p >> 6;
    const int w    = p & 63;

    const float* pb = g_part + (size_t)b * G * 27 * HW;
    float dy   = ob[2 * k];
    float dx   = ob[2 * k + 1];
    float mraw = mb[k];
#pragma unroll
    for (int g = 0; g < G; ++g) {
        dy   += pb[(g * 27 + 2 * k)     * HW + p];
        dx   += pb[(g * 27 + 2 * k + 1) * HW + p];
        mraw += pb[(g * 27 + 18 + k)    * HW + p];
    }
    const float m = 2.f / (1.f + expf(-mraw));

    const float py = dy + (float)(h - 1 + k / 3);
    const float px = dx + (float)(w - 1 + k % 3);
    const float y0f = floorf(py), x0f = floorf(px);
    const float wy1 = py - y0f,  wx1 = px - x0f;
    const float wy0 = 1.f - wy1, wx0 = 1.f - wx1;
    const int y0 = (int)y0f, x0 = (int)x0f;
    const int y1 = y0 + 1,   x1 = x0 + 1;

    int   l0, l1, l2, l3;
    float w0, w1, w2, w3;
    {
        bool v; int yc, xc;
        v = ((unsigned)y0 < 64u) && ((unsigned)x0 < 64u);
        yc = min(max(y0, 0), 63); xc = min(max(x0, 0), 63);
        l0 = yc * 64 + xc; w0 = v ? wy0 * wx0 * m : 0.f;
        v = ((unsigned)y0 < 64u) && ((unsigned)x1 < 64u);
        yc = min(max(y0, 0), 63); xc = min(max(x1, 0), 63);
        l1 = yc * 64 + xc; w1 = v ? wy0 * wx1 * m : 0.f;
        v = ((unsigned)y1 < 64u) && ((unsigned)x0 < 64u);
        yc = min(max(y1, 0), 63); xc = min(max(x0, 0), 63);
        l2 = yc * 64 + xc; w2 = v ? wy1 * wx0 * m : 0.f;
        v = ((unsigned)y1 < 64u) && ((unsigned)x1 < 64u);
        yc = min(max(y1, 0), 63); xc = min(max(x1, 0), 63);
        l3 = yc * 64 + xc; w3 = v ? wy1 * wx1 * m : 0.f;
    }

    const __half* xtb = g_xt + (size_t)b * HW * C;
    const __half* r0 = xtb + (size_t)l0 * C;
    const __half* r1 = xtb + (size_t)l1 * C;
    const __half* r2 = xtb + (size_t)l2 * C;
    const __half* r3 = xtb + (size_t)l3 * C;
    __half* dst = g_vh + ((size_t)b * CK + k) * HW + p;

#pragma unroll 2
    for (int c8 = 0; c8 < C; c8 += 8) {
        float a[8], bb[8], cc[8], dd[8];
        h8_to_f(r0 + c8, a);
        h8_to_f(r1 + c8, bb);
        h8_to_f(r2 + c8, cc);
        h8_to_f(r3 + c8, dd);
#pragma unroll
        for (int j = 0; j < 8; ++j) {
            const float v = w0 * a[j] + w1 * bb[j] + w2 * cc[j] + w3 * dd[j];
            dst[(size_t)(c8 + j) * (9 * HW)] = __float2half_rn(v);
        }
    }
}

// ---------------------------------------------------------------------------
// Kernel 3: fp16 mma.sync GEMM, split-K by 2 (R9 version, unchanged).
// ---------------------------------------------------------------------------
#define BKH    64
#define ATILEB 16384
#define BTILEB 16384
#define STAGEB (ATILEB + BTILEB)
#define NSTAGE 3
#define NCHH   18                        // chunks per K-half
#define GEMM_SMEM (NSTAGE * STAGEB)      // 98304 B

__global__ __launch_bounds__(256, 2)
void gemm_mma_kernel(float* __restrict__ out)
{
    extern __shared__ char smc[];
    const uint32_t sb = smem_u32(smc);

    const int tid  = threadIdx.x;
    const int lane = tid & 31;
    const int wid  = tid >> 5;
    const int bz   = blockIdx.z;
    const int b    = bz >> 1;
    const int kh   = bz & 1;
    const int m0   = blockIdx.y * 128;   // o
    const int n0   = blockIdx.x * 128;   // p

    const __half* gA = g_wh + (size_t)m0 * CK + (size_t)kh * NCHH * BKH;
    const __half* gB = g_vh + (size_t)b * CK * HW + (size_t)kh * NCHH * BKH * HW + n0;

    const int ar  = tid >> 1;
    const int seg = tid & 1;
    const __half* pa = gA + (size_t)ar * CK + seg * 32;
    uint32_t aswo[4];
#pragma unroll
    for (int j = 0; j < 4; ++j)
        aswo[j] = SWZ128((uint32_t)(ar * 128 + seg * 64 + j * 16));

    const int br = tid >> 2;
    const int cg = tid & 3;
    const __half* pv = gB + (size_t)br * HW + cg * 32;
    uint32_t bswo[4];
#pragma unroll
    for (int j = 0; j < 4; ++j) {
        const int cc = cg * 4 + j;
        bswo[j] = ATILEB + (uint32_t)br * 256 + ((uint32_t)(cc ^ (br & 7)) << 4);
    }

#define LOAD_TILE(stage, ch) do {                                             \
        const uint32_t _s = sb + (stage) * STAGEB;                            \
        const __half* _pa = pa + (size_t)(ch) * BKH;                          \
        cp_async16(_s + aswo[0], _pa);                                        \
        cp_async16(_s + aswo[1], _pa + 8);                                    \
        cp_async16(_s + aswo[2], _pa + 16);                                   \
        cp_async16(_s + aswo[3], _pa + 24);                                   \
        const __half* _pv = pv + (size_t)(ch) * BKH * HW;                     \
        cp_async16(_s + bswo[0], _pv);                                        \
        cp_async16(_s + bswo[1], _pv + 8);                                    \
        cp_async16(_s + bswo[2], _pv + 16);                                   \
        cp_async16(_s + bswo[3], _pv + 24);                                   \
    } while (0)

    const int wm = (wid >> 2) * 64;
    const int wn = (wid & 3) * 32;
    uint32_t aOff[4];
#pragma unroll
    for (int mt = 0; mt < 4; ++mt) {
        const uint32_t off = (uint32_t)((wm + mt * 16 + (lane & 15)) * 128
                                        + ((lane & 16) ? 16 : 0));
        aOff[mt] = SWZ128(off);
    }
    const int mIdx = lane >> 3;
    const int koff = ((mIdx & 1) << 3) + (lane & 7);
    const int cc0  = (wn >> 3) + (mIdx >> 1);
    const int cc1  = cc0 + 2;
    const uint32_t bO0 = ATILEB + (uint32_t)koff * 256 + ((uint32_t)(cc0 ^ (koff & 7)) << 4);
    const uint32_t bO1 = ATILEB + (uint32_t)koff * 256 + ((uint32_t)(cc1 ^ (koff & 7)) << 4);

    float c[16][4];
#pragma unroll
    for (int i = 0; i < 16; ++i)
#pragma unroll
        for (int j = 0; j < 4; ++j) c[i][j] = 0.f;

    LOAD_TILE(0, 0); CP_COMMIT();
    LOAD_TILE(1, 1); CP_COMMIT();

    int stage = 0;
    for (int ch = 0; ch < NCHH; ++ch) {
        if (ch + 2 < NCHH) {
            const int ns = (stage + 2 >= NSTAGE) ? stage + 2 - NSTAGE : stage + 2;
            LOAD_TILE(ns, ch + 2);
        }
        CP_COMMIT();
        CP_WAIT(2);
        __syncthreads();

        const uint32_t sbase = sb + stage * STAGEB;
#pragma unroll
        for (int s = 0; s < 4; ++s) {
            uint32_t a[4][4], b0[4], b1[4];
#pragma unroll
            for (int mt = 0; mt < 4; ++mt)
                LDSM4(a[mt], sbase + (aOff[mt] ^ (s << 5)));
            LDSM4T(b0, sbase + bO0 + s * 4096);
            LDSM4T(b1, sbase + bO1 + s * 4096);
#pragma unroll
            for (int mt = 0; mt < 4; ++mt) {
                mma16816(c[mt * 4 + 0], a[mt], &b0[0]);
                mma16816(c[mt * 4 + 1], a[mt], &b0[2]);
                mma16816(c[mt * 4 + 2], a[mt], &b1[0]);
                mma16816(c[mt * 4 + 3], a[mt], &b1[2]);
            }
        }
        __syncthreads();
        stage = (stage + 1 >= NSTAGE) ? 0 : stage + 1;
    }

    float* dstb = (kh == 0) ? out : g_po;
    const int qr = lane >> 2;
    const int qc = lane & 3;
#pragma unroll
    for (int mt = 0; mt < 4; ++mt) {
#pragma unroll
        for (int nt = 0; nt < 4; ++nt) {
            const int o = m0 + wm + mt * 16 + qr;
            const int p = n0 + wn + nt * 8 + 2 * qc;
            float* o0 = dstb + ((size_t)(b * CO + o)) * HW + p;
            float2 v0; v0.x = c[mt * 4 + nt][0]; v0.y = c[mt * 4 + nt][1];
            *(float2*)o0 = v0;
            float2 v1; v1.x = c[mt * 4 + nt][2]; v1.y = c[mt * 4 + nt][3];
            *(float2*)(o0 + 8 * HW) = v1;
        }
    }
}

// ---------------------------------------------------------------------------
// Kernel 4: split-K reduce  out += g_po   (2x float4 per thread)
// ---------------------------------------------------------------------------
__global__ __launch_bounds__(256)
void reduce_kernel(float* __restrict__ out)
{
    const int i = (blockIdx.x * 256 + threadIdx.x) * 2;   // 1024 blocks
    float4 a0 = ((float4*)out)[i];
    float4 a1 = ((float4*)out)[i + 1];
    const float4 p0 = ((const float4*)g_po)[i];
    const float4 p1 = ((const float4*)g_po)[i + 1];
    a0.x += p0.x; a0.y += p0.y; a0.z += p0.z; a0.w += p0.w;
    a1.x += p1.x; a1.y += p1.y; a1.z += p1.z; a1.w += p1.w;
    ((float4*)out)[i]     = a0;
    ((float4*)out)[i + 1] = a1;
}

// ---------------------------------------------------------------------------
extern "C" void kernel_launch(void* const* d_in, const int* in_sizes, int n_in,
                              void* d_out, int out_size)
{
    const float* x   = (const float*)d_in[0];   // [2,256,64,64]
    const float* res = (const float*)d_in[1];   // [2,256,64,64]
    const float* ow  = (const float*)d_in[2];   // [18,256,3,3]
    const float* ob  = (const float*)d_in[3];   // [18]
    const float* mw  = (const float*)d_in[4];   // [9,256,3,3]
    const float* mb  = (const float*)d_in[5];   // [9]
    const float* rw  = (const float*)d_in[6];   // [256,256,3,3]
    float* out = (float*)d_out;                 // [2,256,64,64]

    static int smem_set = 0;
    if (!smem_set) {
        cudaFuncSetAttribute(gemm_mma_kernel,
                             cudaFuncAttributeMaxDynamicSharedMemorySize, GEMM_SMEM);
        smem_set = 1;
    }

    conv_offmod_kernel<<<1424, 128>>>(x, res, ow, mw, rw);
    sample_kernel<<<dim3(HW / 32, BATCH), 288>>>(ob, mb);
    gemm_mma_kernel<<<dim3(HW / 128, CO / 128, BATCH * 2), 256, GEMM_SMEM>>>(out);
    reduce_kernel<<<BATCH * CO * HW / 8 / 256, 256>>>(out);
}

// round 12
// speedup vs baseline: 1.1060x; 1.1060x over previous
#include <cuda_runtime.h>
#include <cuda_fp16.h>
#include <cstdint>
#include <math.h>

// Problem constants
#define BATCH 2
#define C 256
#define H 64
#define W 64
#define HW 4096
#define K2 9
#define CO 256
#define CK 2304        // C*K2
#define G 16           // channel groups for conv partial sums (16 ch each)

// Scratch (__device__ globals; allocation-free rule)
__device__ float  g_part[BATCH * G * 27 * HW];     // [b][g][o(27)][p]
__device__ __half g_vh[(size_t)BATCH * CK * HW];   // [b][ck][p]  p-contiguous fp16
__device__ __half g_wh[(size_t)CO * CK];           // W fp16, K-major rows of o
__device__ __half g_xt[(size_t)BATCH * HW * C];    // x transposed: [b][p][c] fp16
__device__ float  g_po[(size_t)BATCH * CO * HW];   // split-K partial output

// ---------------------------------------------------------------------------
// helpers
// ---------------------------------------------------------------------------
__device__ __forceinline__ uint32_t smem_u32(const void* p) {
    uint32_t a;
    asm("{ .reg .u64 t; cvta.to.shared.u64 t, %1; cvt.u32.u64 %0, t; }" : "=r"(a) : "l"(p));
    return a;
}
__device__ __forceinline__ void cp_async16(uint32_t dst, const void* src) {
    asm volatile("cp.async.cg.shared.global [%0], [%1], 16;" :: "r"(dst), "l"(src));
}
#define CP_COMMIT() asm volatile("cp.async.commit_group;" ::: "memory")
#define CP_WAIT(n)  asm volatile("cp.async.wait_group %0;" :: "n"(n) : "memory")
#define SWZ128(off) ((off) ^ (((off) >> 3) & 0x70))

#define LDSM4(r, addr) \
    asm volatile("ldmatrix.sync.aligned.m8n8.x4.shared.b16 {%0,%1,%2,%3}, [%4];" \
        : "=r"((r)[0]), "=r"((r)[1]), "=r"((r)[2]), "=r"((r)[3]) : "r"(addr))
#define LDSM4T(r, addr) \
    asm volatile("ldmatrix.sync.aligned.m8n8.x4.trans.shared.b16 {%0,%1,%2,%3}, [%4];" \
        : "=r"((r)[0]), "=r"((r)[1]), "=r"((r)[2]), "=r"((r)[3]) : "r"(addr))

__device__ __forceinline__ void mma16816(float c[4], const uint32_t a[4], const uint32_t b[2]) {
    asm volatile(
        "mma.sync.aligned.m16n8k16.row.col.f32.f16.f16.f32 "
        "{%0,%1,%2,%3}, {%4,%5,%6,%7}, {%8,%9}, {%0,%1,%2,%3};"
        : "+f"(c[0]), "+f"(c[1]), "+f"(c[2]), "+f"(c[3])
        : "r"(a[0]), "r"(a[1]), "r"(a[2]), "r"(a[3]), "r"(b[0]), "r"(b[1]));
}

__device__ __forceinline__ void h8f(const uint4 v, float* f) {
    const __half2* h = (const __half2*)&v;
#pragma unroll
    for (int j = 0; j < 4; ++j) {
        const float2 t = __half22float2(h[j]);
        f[2 * j] = t.x; f[2 * j + 1] = t.y;
    }
}

// ---------------------------------------------------------------------------
// Kernel 1: blocks 0..255 conv (offset 18ch from res + mod 9ch from x);
// blocks 256..399 W->fp16; blocks 400..1423 transpose x -> g_xt[b][p][c] fp16.
// ---------------------------------------------------------------------------
__global__ __launch_bounds__(128)
void conv_offmod_kernel(const float* __restrict__ x,
                        const float* __restrict__ res,
                        const float* __restrict__ ow,   // [18][C][9]
                        const float* __restrict__ mw,   // [9][C][9]
                        const float* __restrict__ rw)   // [256][C][9]
{
    __shared__ __align__(16) float sw[16 * 27 * 12];    // 5184 floats (>= 64*33)

    const int tid  = threadIdx.x;
    const int bidx = blockIdx.x;

    if (bidx >= 400) {
        // transpose: tile 64 c x 32 p
        const int t  = bidx - 400;                 // 0..1023
        const int p0 = (t & 127) * 32;
        const int c0 = ((t >> 7) & 3) * 64;
        const int b  = t >> 9;
        float (*s32)[33] = (float(*)[33])sw;
        const int lane = tid & 31;
        const int wi   = tid >> 5;                 // 0..3
        const float* xb = x + ((size_t)(b * C + c0)) * HW + p0;
#pragma unroll
        for (int i = 0; i < 16; ++i) {
            const int cl = wi * 16 + i;
            s32[cl][lane] = xb[(size_t)cl * HW + lane];
        }
        __syncthreads();
        __half2* dst = (__half2*)(g_xt + ((size_t)(b * HW + p0)) * C + c0);
#pragma unroll
        for (int i = 0; i < 8; ++i) {
            const int pl = wi * 8 + i;
            dst[(size_t)pl * (C / 2) + lane] =
                __floats2half2_rn(s32[lane * 2][pl], s32[lane * 2 + 1][pl]);
        }
        return;
    }

    if (bidx >= 256) {
        // fused prep_w: convert reg_w to fp16
        const int n4 = CO * CK / 4;                // 147456 float4
        for (int i = (bidx - 256) * 128 + tid; i < n4; i += 144 * 128) {
            const float4 v = ((const float4*)rw)[i];
            __half2* dst = (__half2*)(g_wh + (size_t)i * 4);
            dst[0] = __floats2half2_rn(v.x, v.y);
            dst[1] = __floats2half2_rn(v.z, v.w);
        }
        return;
    }

    const int pblk = bidx & 7;
    const int g    = (bidx >> 3) & (G - 1);
    const int b    = bidx >> 7;
    const int p    = pblk * 512 + tid * 4;
    const int h    = p >> 6;
    const int w    = p & 63;

    const int cbase = g * 16;
    for (int i = tid; i < 16 * 243; i += 128) {
        const int ci = i / 243;
        const int t  = i % 243;
        const int c  = cbase + ci;
        const int o  = t / 9;
        const int tt = t % 9;
        float wv;
        if (o < 18) wv = ow[(size_t)o * CK + c * 9 + tt];
        else        wv = mw[(size_t)(o - 18) * CK + c * 9 + tt];
        sw[ci * 324 + o * 12 + tt] = wv;
    }
    __syncthreads();

    float* outp = g_part + (size_t)(b * G + g) * 27 * HW;

    // Pass A: 18 offset outputs from residual
    {
        float acc[18][4];
#pragma unroll
        for (int o = 0; o < 18; ++o)
#pragma unroll
            for (int j = 0; j < 4; ++j) acc[o][j] = 0.f;

        const float* rb = res + (size_t)b * C * HW;
        for (int ci = 0; ci < 16; ++ci) {
            const float* rc = rb + (size_t)(cbase + ci) * HW;
            float rv[18];
#pragma unroll
            for (int r = 0; r < 3; ++r) {
                const int hh = h + r - 1;
                const bool vy = ((unsigned)hh < 64u);
#pragma unroll
                for (int s = 0; s < 6; ++s) {
                    const int ww = w + s - 1;
                    const bool v = vy && ((unsigned)ww < 64u);
                    rv[r * 6 + s] = v ? rc[hh * 64 + ww] : 0.f;
                }
            }
            const float* swc = sw + ci * 324;
#pragma unroll
            for (int o = 0; o < 18; ++o) {
                const float4 wA = *(const float4*)(swc + o * 12);
                const float4 wB = *(const float4*)(swc + o * 12 + 4);
                const float  w8 = swc[o * 12 + 8];
#pragma unroll
                for (int j = 0; j < 4; ++j) {
                    acc[o][j] += wA.x * rv[j]      + wA.y * rv[j + 1]  + wA.z * rv[j + 2]
                               + wA.w * rv[j + 6]  + wB.x * rv[j + 7]  + wB.y * rv[j + 8]
                               + wB.z * rv[j + 12] + wB.w * rv[j + 13] + w8  * rv[j + 14];
                }
            }
        }
#pragma unroll
        for (int o = 0; o < 18; ++o) {
            float4 v; v.x = acc[o][0]; v.y = acc[o][1]; v.z = acc[o][2]; v.w = acc[o][3];
            *(float4*)(outp + o * HW + p) = v;
        }
    }

    // Pass B: 9 modulator outputs from x
    {
        float acc[9][4];
#pragma unroll
        for (int o = 0; o < 9; ++o)
#pragma unroll
            for (int j = 0; j < 4; ++j) acc[o][j] = 0.f;

        const float* xb = x + (size_t)b * C * HW;
        for (int ci = 0; ci < 16; ++ci) {
            const float* xc = xb + (size_t)(cbase + ci) * HW;
            float xv[18];
#pragma unroll
            for (int r = 0; r < 3; ++r) {
                const int hh = h + r - 1;
                const bool vy = ((unsigned)hh < 64u);
#pragma unroll
                for (int s = 0; s < 6; ++s) {
                    const int ww = w + s - 1;
                    const bool v = vy && ((unsigned)ww < 64u);
                    xv[r * 6 + s] = v ? xc[hh * 64 + ww] : 0.f;
                }
            }
            const float* swc = sw + ci * 324;
#pragma unroll
            for (int o = 0; o < 9; ++o) {
                const float4 wA = *(const float4*)(swc + (18 + o) * 12);
                const float4 wB = *(const float4*)(swc + (18 + o) * 12 + 4);
                const float  w8 = swc[(18 + o) * 12 + 8];
#pragma unroll
                for (int j = 0; j < 4; ++j) {
                    acc[o][j] += wA.x * xv[j]      + wA.y * xv[j + 1]  + wA.z * xv[j + 2]
                               + wA.w * xv[j + 6]  + wB.x * xv[j + 7]  + wB.y * xv[j + 8]
                               + wB.z * xv[j + 12] + wB.w * xv[j + 13] + w8  * xv[j + 14];
                }
            }
        }
#pragma unroll
        for (int o = 0; o < 9; ++o) {
            float4 v; v.x = acc[o][0]; v.y = acc[o][1]; v.z = acc[o][2]; v.w = acc[o][3];
            *(float4*)(outp + (18 + o) * HW + p) = v;
        }
    }
}

// ---------------------------------------------------------------------------
// Kernel 2: sampling v3 — warp = (pixel,tap) pair, lanes split channels.
// Block = 32 pixels x 9 taps = 288 pairs, 256 threads.
// Phase 0: offsets/weights for 288 pairs -> smem.
// Phase A (per 64-ch chunk): 8-lane groups read one 128B line per tap from
// g_xt[b][p][c]; combine; stage fp16 in sv[pair][64].
// Phase B: write g_vh[b][ck][p] with lane = pixel (64B coalesced stores).
// NOTE: needs MaxDynamicSharedMemorySize opt-in (static 9216B + dyn 41472B).
// ---------------------------------------------------------------------------
#define SVROW 36   // uint32 words per sv row (144B = 128B data + 16B pad)
#define SAMPLE_DSMEM (288 * SVROW * 4)   // 41472 B
__global__ __launch_bounds__(256)
void sample_kernel(const float* __restrict__ ob,   // [18]
                   const float* __restrict__ mb)   // [9]
{
    __shared__ int   sl0[288], sl1[288], sl2[288], sl3[288];
    __shared__ float sw0[288], sw1[288], sw2[288], sw3[288];
    extern __shared__ uint32_t sv[];               // 288 * 36 words = 41472 B

    const int tid  = threadIdx.x;
    const int lane = tid & 31;
    const int wid  = tid >> 5;           // 0..7
    const int b    = blockIdx.y;
    const int p0   = blockIdx.x * 32;

    // ---- Phase 0: per-(pixel,tap) coords + modulated weights ----
    const float* pb = g_part + (size_t)b * G * 27 * HW;
    for (int pk = tid; pk < 288; pk += 256) {
        const int px = pk / 9;
        const int k  = pk - px * 9;
        const int p  = p0 + px;
        const int h  = p >> 6;
        const int w  = p & 63;

        float dy   = ob[2 * k];
        float dx   = ob[2 * k + 1];
        float mraw = mb[k];
#pragma unroll
        for (int g = 0; g < G; ++g) {
            dy   += pb[(g * 27 + 2 * k)     * HW + p];
            dx   += pb[(g * 27 + 2 * k + 1) * HW + p];
            mraw += pb[(g * 27 + 18 + k)    * HW + p];
        }
        const float m = 2.f / (1.f + expf(-mraw));

        const float py  = dy + (float)(h - 1 + k / 3);
        const float px_ = dx + (float)(w - 1 + k % 3);
        const float y0f = floorf(py), x0f = floorf(px_);
        const float wy1 = py - y0f,  wx1 = px_ - x0f;
        const float wy0 = 1.f - wy1, wx0 = 1.f - wx1;
        const int y0 = (int)y0f, x0 = (int)x0f;
        const int y1 = y0 + 1,   x1 = x0 + 1;

        bool v; int yc, xc;
        v = ((unsigned)y0 < 64u) && ((unsigned)x0 < 64u);
        yc = min(max(y0, 0), 63); xc = min(max(x0, 0), 63);
        sl0[pk] = yc * 64 + xc; sw0[pk] = v ? wy0 * wx0 * m : 0.f;
        v = ((unsigned)y0 < 64u) && ((unsigned)x1 < 64u);
        yc = min(max(y0, 0), 63); xc = min(max(x1, 0), 63);
        sl1[pk] = yc * 64 + xc; sw1[pk] = v ? wy0 * wx1 * m : 0.f;
        v = ((unsigned)y1 < 64u) && ((unsigned)x0 < 64u);
        yc = min(max(y1, 0), 63); xc = min(max(x0, 0), 63);
        sl2[pk] = yc * 64 + xc; sw2[pk] = v ? wy1 * wx0 * m : 0.f;
        v = ((unsigned)y1 < 64u) && ((unsigned)x1 < 64u);
        yc = min(max(y1, 0), 63); xc = min(max(x1, 0), 63);
        sl3[pk] = yc * 64 + xc; sw3[pk] = v ? wy1 * wx1 * m : 0.f;
    }
    __syncthreads();

    const __half* xtb = g_xt + (size_t)b * HW * C;
    const int grp = lane >> 3;           // 0..3 (pair within quad)
    const int lg  = lane & 7;            // channel-lane within group

    for (int c0 = 0; c0 < C; c0 += 64) {
        // ---- Phase A: gather + combine into sv ----
#pragma unroll
        for (int i = 0; i < 9; ++i) {
            const int pk = wid * 36 + i * 4 + grp;
            const int c  = c0 + lg * 8;
            const float w0 = sw0[pk], w1 = sw1[pk], w2 = sw2[pk], w3 = sw3[pk];
            const uint4 v0 = *(const uint4*)(xtb + (size_t)sl0[pk] * C + c);
            const uint4 v1 = *(const uint4*)(xtb + (size_t)sl1[pk] * C + c);
            const uint4 v2 = *(const uint4*)(xtb + (size_t)sl2[pk] * C + c);
            const uint4 v3 = *(const uint4*)(xtb + (size_t)sl3[pk] * C + c);
            float a[8], bb[8], cc[8], dd[8];
            h8f(v0, a); h8f(v1, bb); h8f(v2, cc); h8f(v3, dd);
            uint4 o;
            __half2* oh = (__half2*)&o;
#pragma unroll
            for (int j = 0; j < 4; ++j) {
                const float f0 = w0 * a[2*j]   + w1 * bb[2*j]   + w2 * cc[2*j]   + w3 * dd[2*j];
                const float f1 = w0 * a[2*j+1] + w1 * bb[2*j+1] + w2 * cc[2*j+1] + w3 * dd[2*j+1];
                oh[j] = __floats2half2_rn(f0, f1);
            }
            *(uint4*)(sv + pk * SVROW + lg * 4) = o;
        }
        __syncthreads();

        // ---- Phase B: coalesced write-out (lane = pixel) ----
        const __half* svh = (const __half*)sv;
        for (int t = 0; t < 72; ++t) {
            const int r  = wid * 72 + t;           // 0..575
            const int k  = r >> 6;                 // 0..8
            const int cl = r & 63;                 // 0..63
            const __half val = svh[(size_t)(lane * 9 + k) * (SVROW * 2) + cl];
            g_vh[((size_t)b * CK + (size_t)(c0 + cl) * 9 + k) * HW + p0 + lane] = val;
        }
        __syncthreads();
    }
}

// ---------------------------------------------------------------------------
// Kernel 3: fp16 mma.sync GEMM, split-K by 2 (R9 version, unchanged).
// ---------------------------------------------------------------------------
#define BKH    64
#define ATILEB 16384
#define BTILEB 16384
#define STAGEB (ATILEB + BTILEB)
#define NSTAGE 3
#define NCHH   18                        // chunks per K-half
#define GEMM_SMEM (NSTAGE * STAGEB)      // 98304 B

__global__ __launch_bounds__(256, 2)
void gemm_mma_kernel(float* __restrict__ out)
{
    extern __shared__ char smc[];
    const uint32_t sb = smem_u32(smc);

    const int tid  = threadIdx.x;
    const int lane = tid & 31;
    const int wid  = tid >> 5;
    const int bz   = blockIdx.z;
    const int b    = bz >> 1;
    const int kh   = bz & 1;
    const int m0   = blockIdx.y * 128;   // o
    const int n0   = blockIdx.x * 128;   // p

    const __half* gA = g_wh + (size_t)m0 * CK + (size_t)kh * NCHH * BKH;
    const __half* gB = g_vh + (size_t)b * CK * HW + (size_t)kh * NCHH * BKH * HW + n0;

    const int ar  = tid >> 1;
    const int seg = tid & 1;
    const __half* pa = gA + (size_t)ar * CK + seg * 32;
    uint32_t aswo[4];
#pragma unroll
    for (int j = 0; j < 4; ++j)
        aswo[j] = SWZ128((uint32_t)(ar * 128 + seg * 64 + j * 16));

    const int br = tid >> 2;
    const int cg = tid & 3;
    const __half* pv = gB + (size_t)br * HW + cg * 32;
    uint32_t bswo[4];
#pragma unroll
    for (int j = 0; j < 4; ++j) {
        const int cc = cg * 4 + j;
        bswo[j] = ATILEB + (uint32_t)br * 256 + ((uint32_t)(cc ^ (br & 7)) << 4);
    }

#define LOAD_TILE(stage, ch) do {                                             \
        const uint32_t _s = sb + (stage) * STAGEB;                            \
        const __half* _pa = pa + (size_t)(ch) * BKH;                          \
        cp_async16(_s + aswo[0], _pa);                                        \
        cp_async16(_s + aswo[1], _pa + 8);                                    \
        cp_async16(_s + aswo[2], _pa + 16);                                   \
        cp_async16(_s + aswo[3], _pa + 24);                                   \
        const __half* _pv = pv + (size_t)(ch) * BKH * HW;                     \
        cp_async16(_s + bswo[0], _pv);                                        \
        cp_async16(_s + bswo[1], _pv + 8);                                    \
        cp_async16(_s + bswo[2], _pv + 16);                                   \
        cp_async16(_s + bswo[3], _pv + 24);                                   \
    } while (0)

    const int wm = (wid >> 2) * 64;
    const int wn = (wid & 3) * 32;
    uint32_t aOff[4];
#pragma unroll
    for (int mt = 0; mt < 4; ++mt) {
        const uint32_t off = (uint32_t)((wm + mt * 16 + (lane & 15)) * 128
                                        + ((lane & 16) ? 16 : 0));
        aOff[mt] = SWZ128(off);
    }
    const int mIdx = lane >> 3;
    const int koff = ((mIdx & 1) << 3) + (lane & 7);
    const int cc0  = (wn >> 3) + (mIdx >> 1);
    const int cc1  = cc0 + 2;
    const uint32_t bO0 = ATILEB + (uint32_t)koff * 256 + ((uint32_t)(cc0 ^ (koff & 7)) << 4);
    const uint32_t bO1 = ATILEB + (uint32_t)koff * 256 + ((uint32_t)(cc1 ^ (koff & 7)) << 4);

    float c[16][4];
#pragma unroll
    for (int i = 0; i < 16; ++i)
#pragma unroll
        for (int j = 0; j < 4; ++j) c[i][j] = 0.f;

    LOAD_TILE(0, 0); CP_COMMIT();
    LOAD_TILE(1, 1); CP_COMMIT();

    int stage = 0;
    for (int ch = 0; ch < NCHH; ++ch) {
        if (ch + 2 < NCHH) {
            const int ns = (stage + 2 >= NSTAGE) ? stage + 2 - NSTAGE : stage + 2;
            LOAD_TILE(ns, ch + 2);
        }
        CP_COMMIT();
        CP_WAIT(2);
        __syncthreads();

        const uint32_t sbase = sb + stage * STAGEB;
#pragma unroll
        for (int s = 0; s < 4; ++s) {
            uint32_t a[4][4], b0[4], b1[4];
#pragma unroll
            for (int mt = 0; mt < 4; ++mt)
                LDSM4(a[mt], sbase + (aOff[mt] ^ (s << 5)));
            LDSM4T(b0, sbase + bO0 + s * 4096);
            LDSM4T(b1, sbase + bO1 + s * 4096);
#pragma unroll
            for (int mt = 0; mt < 4; ++mt) {
                mma16816(c[mt * 4 + 0], a[mt], &b0[0]);
                mma16816(c[mt * 4 + 1], a[mt], &b0[2]);
                mma16816(c[mt * 4 + 2], a[mt], &b1[0]);
                mma16816(c[mt * 4 + 3], a[mt], &b1[2]);
            }
        }
        __syncthreads();
        stage = (stage + 1 >= NSTAGE) ? 0 : stage + 1;
    }

    float* dstb = (kh == 0) ? out : g_po;
    const int qr = lane >> 2;
    const int qc = lane & 3;
#pragma unroll
    for (int mt = 0; mt < 4; ++mt) {
#pragma unroll
        for (int nt = 0; nt < 4; ++nt) {
            const int o = m0 + wm + mt * 16 + qr;
            const int p = n0 + wn + nt * 8 + 2 * qc;
            float* o0 = dstb + ((size_t)(b * CO + o)) * HW + p;
            float2 v0; v0.x = c[mt * 4 + nt][0]; v0.y = c[mt * 4 + nt][1];
            *(float2*)o0 = v0;
            float2 v1; v1.x = c[mt * 4 + nt][2]; v1.y = c[mt * 4 + nt][3];
            *(float2*)(o0 + 8 * HW) = v1;
        }
    }
}

// ---------------------------------------------------------------------------
// Kernel 4: split-K reduce  out += g_po   (float4; R9 version)
// ---------------------------------------------------------------------------
__global__ __launch_bounds__(256)
void reduce_kernel(float* __restrict__ out)
{
    const int i = blockIdx.x * 256 + threadIdx.x;    // BATCH*CO*HW/4 = 524288
    float4 a = ((float4*)out)[i];
    const float4 p = ((const float4*)g_po)[i];
    a.x += p.x; a.y += p.y; a.z += p.z; a.w += p.w;
    ((float4*)out)[i] = a;
}

// ---------------------------------------------------------------------------
extern "C" void kernel_launch(void* const* d_in, const int* in_sizes, int n_in,
                              void* d_out, int out_size)
{
    const float* x   = (const float*)d_in[0];   // [2,256,64,64]
    const float* res = (const float*)d_in[1];   // [2,256,64,64]
    const float* ow  = (const float*)d_in[2];   // [18,256,3,3]
    const float* ob  = (const float*)d_in[3];   // [18]
    const float* mw  = (const float*)d_in[4];   // [9,256,3,3]
    const float* mb  = (const float*)d_in[5];   // [9]
    const float* rw  = (const float*)d_in[6];   // [256,256,3,3]
    float* out = (float*)d_out;                 // [2,256,64,64]

    static int smem_set = 0;
    if (!smem_set) {
        cudaFuncSetAttribute(gemm_mma_kernel,
                             cudaFuncAttributeMaxDynamicSharedMemorySize, GEMM_SMEM);
        cudaFuncSetAttribute(sample_kernel,
                             cudaFuncAttributeMaxDynamicSharedMemorySize, SAMPLE_DSMEM);
        smem_set = 1;
    }

    conv_offmod_kernel<<<1424, 128>>>(x, res, ow, mw, rw);
    sample_kernel<<<dim3(HW / 32, BATCH), 256, SAMPLE_DSMEM>>>(ob, mb);
    gemm_mma_kernel<<<dim3(HW / 128, CO / 128, BATCH * 2), 256, GEMM_SMEM>>>(out);
    reduce_kernel<<<BATCH * CO * HW / 4 / 256, 256>>>(out);
}